// round 6
// baseline (speedup 1.0000x reference)
#include <cuda_runtime.h>
#include <cstdint>

#define N_NODES 100000
#define N_EDGES 3200000
#define N_GRAPHS 512
#define IN_CH 50
#define HID 256
#define KDIM 100            // concatenated feature dim: [x(50) | agg(50)]
#define TILE_N 64           // nodes per block in fused GEMM
#define KC 25               // k-rows per smem chunk
#define NCHUNK 4            // KDIM / KC
#define FS_STRIDE 68        // padded Fs row (floats), 17 float4

// ---------------- device scratch ----------------
__device__ __align__(16) float g_agg[N_NODES * IN_CH];     // 20 MB neighbor sums
__device__ __align__(16) float g_cnt[N_NODES];             // edges per dst node
__device__ __align__(16) float g_pooled[N_GRAPHS * HID];   // per-graph h sums
__device__ __align__(16) float g_gcnt[N_GRAPHS];           // nodes per graph

// ---------------- kernel 0: zero scratch ----------------
__global__ __launch_bounds__(256) void zero_scratch()
{
    int i = blockIdx.x * blockDim.x + threadIdx.x;
    int stride = gridDim.x * blockDim.x;
    for (; i < N_NODES * IN_CH / 4; i += stride)
        ((float4*)g_agg)[i] = make_float4(0.f, 0.f, 0.f, 0.f);
    for (i = blockIdx.x * blockDim.x + threadIdx.x; i < N_NODES; i += stride)
        g_cnt[i] = 0.f;
    for (i = blockIdx.x * blockDim.x + threadIdx.x; i < N_GRAPHS * HID; i += stride)
        g_pooled[i] = 0.f;
    for (i = blockIdx.x * blockDim.x + threadIdx.x; i < N_GRAPHS; i += stride)
        g_gcnt[i] = 0.f;
}

// ---------------- kernel 1: edge scatter-mean (sum + count) ----------------
// One warp owns 32 consecutive edges (3.2M % 32 == 0). Coalesced int32 index
// loads, shfl broadcast; lanes 0..24 each move one float2 (REDG.64), lane 25
// bumps the per-dst count.
__global__ __launch_bounds__(256) void edge_scatter(
    const int* __restrict__ ei, const float* __restrict__ x)
{
    int warp = (blockIdx.x * blockDim.x + threadIdx.x) >> 5;
    int lane = threadIdx.x & 31;
    int e = warp * 32 + lane;
    int s = ei[e];
    int d = ei[N_EDGES + e];
    const float2* x2 = (const float2*)x;
    #pragma unroll 4
    for (int i = 0; i < 32; i++) {
        int si = __shfl_sync(0xffffffffu, s, i);
        int di = __shfl_sync(0xffffffffu, d, i);
        if (lane < 25) {
            float2 v = x2[si * 25 + lane];
            atomicAdd((float2*)&g_agg[di * IN_CH + lane * 2], v);
        } else if (lane == 25) {
            atomicAdd(&g_cnt[di], 1.0f);
        }
    }
}

// ---------------- kernel 2: nodes per graph (atomic-free) ------------------
// batch is sorted; the thread at each run boundary scans its run and stores
// the count directly.
__global__ __launch_bounds__(256) void count_nodes(const int* __restrict__ batch)
{
    int i = blockIdx.x * blockDim.x + threadIdx.x;
    if (i >= N_NODES) return;
    int g = batch[i];
    if (i == 0 || batch[i - 1] != g) {
        int j = i + 1;
        while (j < N_NODES && batch[j] == g) j++;
        g_gcnt[g] = (float)(j - i);
    }
}

// ---------------- kernel 3: fused node GEMM + leakyReLU + pool-scatter -----
// Block: 256 threads, 64 nodes x 256 channels. Thread = 8 ch x 8 nodes.
// K processed in 4 chunks of 25 rows; static smem ~33 KB (<48 KB, no opt-in).
__global__ __launch_bounds__(256) void node_fused(
    const float* __restrict__ x,
    const int* __restrict__ batch,
    const float* __restrict__ W_l, const float* __restrict__ b_l,
    const float* __restrict__ W_r)
{
    __shared__ float sW[KC * HID];          // 25600 B
    __shared__ float sF[KC * FS_STRIDE];    // 6800 B
    __shared__ float sInv[TILE_N];
    __shared__ int   sGid[TILE_N];

    int tid = threadIdx.x;
    int n0  = blockIdx.x * TILE_N;

    if (tid < TILE_N) {
        int node = n0 + tid;
        float c = 1.0f; int g = -1;
        if (node < N_NODES) { c = g_cnt[node]; g = batch[node]; }
        sInv[tid] = 1.0f / fmaxf(c, 1.0f);
        sGid[tid] = g;
    }

    int tc = tid & 31;   // channels tc*4..+3 and 128+tc*4..+3
    int tn = tid >> 5;   // nodes tn*8..tn*8+7

    float acc[8][8];
    #pragma unroll
    for (int a = 0; a < 8; a++)
        #pragma unroll
        for (int b = 0; b < 8; b++) acc[a][b] = 0.0f;

    const float4* sW4 = (const float4*)sW;   // row = 64 float4
    const float4* sF4 = (const float4*)sF;   // row = 17 float4

    for (int kc = 0; kc < NCHUNK; kc++) {
        __syncthreads();
        // stage weights chunk: sW[kk][c], global k = kc*25+kk
        for (int idx = tid; idx < KC * HID; idx += 256) {
            int c  = idx / KC;
            int kk = idx - c * KC;
            int k  = kc * KC + kk;
            float v = (k < IN_CH) ? W_r[c * IN_CH + k]
                                  : W_l[c * IN_CH + k - IN_CH];
            sW[kk * HID + c] = v;
        }
        // stage feature chunk: sF[kk][n]
        for (int idx = tid; idx < KC * TILE_N; idx += 256) {
            int n  = idx / KC;
            int kk = idx - n * KC;
            int k  = kc * KC + kk;
            int node = n0 + n;
            float v = 0.0f;
            if (node < N_NODES) {
                v = (k < IN_CH) ? x[node * IN_CH + k]
                                : g_agg[node * IN_CH + k - IN_CH] * sInv[n];
            }
            sF[kk * FS_STRIDE + n] = v;
        }
        __syncthreads();

        #pragma unroll
        for (int kk = 0; kk < KC; kk++) {
            float4 w0 = sW4[kk * 64 + tc];
            float4 w1 = sW4[kk * 64 + 32 + tc];
            float4 f0 = sF4[kk * 17 + tn * 2];
            float4 f1 = sF4[kk * 17 + tn * 2 + 1];
            float w[8] = {w0.x, w0.y, w0.z, w0.w, w1.x, w1.y, w1.z, w1.w};
            float f[8] = {f0.x, f0.y, f0.z, f0.w, f1.x, f1.y, f1.z, f1.w};
            #pragma unroll
            for (int a = 0; a < 8; a++)
                #pragma unroll
                for (int b = 0; b < 8; b++)
                    acc[a][b] += w[a] * f[b];
        }
    }

    // epilogue: bias + leakyReLU, then run-merged scalar REDs into g_pooled.
    // batch sorted -> a thread's 8 nodes span few graphs; flush per run.
    const float4* bl4 = (const float4*)b_l;
    float4 bA = bl4[tc];
    float4 bB = bl4[32 + tc];
    float bias[8] = {bA.x, bA.y, bA.z, bA.w, bB.x, bB.y, bB.z, bB.w};
    int ch[8];
    #pragma unroll
    for (int a = 0; a < 4; a++) { ch[a] = tc * 4 + a; ch[4 + a] = 128 + tc * 4 + a; }

    float run[8];
    #pragma unroll
    for (int a = 0; a < 8; a++) run[a] = 0.0f;
    int runG = sGid[tn * 8];

    #pragma unroll
    for (int j = 0; j < 8; j++) {
        int g = sGid[tn * 8 + j];
        if (g != runG) {
            if (runG >= 0) {
                #pragma unroll
                for (int a = 0; a < 8; a++)
                    atomicAdd(&g_pooled[runG * HID + ch[a]], run[a]);
            }
            #pragma unroll
            for (int a = 0; a < 8; a++) run[a] = 0.0f;
            runG = g;
        }
        if (g >= 0) {
            #pragma unroll
            for (int a = 0; a < 8; a++) {
                float h = acc[a][j] + bias[a];
                h = h > 0.f ? h : 0.01f * h;
                run[a] += h;
            }
        }
    }
    if (runG >= 0) {
        #pragma unroll
        for (int a = 0; a < 8; a++)
            atomicAdd(&g_pooled[runG * HID + ch[a]], run[a]);
    }
}

// ---------------- kernel 4: pooled mean + classifier ----------------
__global__ __launch_bounds__(256) void finalize(
    const float* __restrict__ W_c, const float* __restrict__ b_c,
    float* __restrict__ out)
{
    int g = blockIdx.x;
    int t = threadIdx.x;
    float inv = 1.0f / fmaxf(g_gcnt[g], 1.0f);
    float p = g_pooled[g * HID + t] * inv;
    float s0 = p * W_c[t];
    float s1 = p * W_c[HID + t];
    #pragma unroll
    for (int off = 16; off > 0; off >>= 1) {
        s0 += __shfl_down_sync(0xffffffffu, s0, off);
        s1 += __shfl_down_sync(0xffffffffu, s1, off);
    }
    __shared__ float sh0[8], sh1[8];
    int lane = t & 31, wid = t >> 5;
    if (lane == 0) { sh0[wid] = s0; sh1[wid] = s1; }
    __syncthreads();
    if (t == 0) {
        float t0 = b_c[0], t1 = b_c[1];
        #pragma unroll
        for (int w = 0; w < 8; w++) { t0 += sh0[w]; t1 += sh1[w]; }
        out[g * 2 + 0] = t0;
        out[g * 2 + 1] = t1;
    }
}

// ---------------- launch: kernel launches ONLY ----------------
extern "C" void kernel_launch(void* const* d_in, const int* in_sizes, int n_in,
                              void* d_out, int out_size)
{
    const float* x     = (const float*)d_in[0];
    const int*   ei    = (const int*)d_in[1];    // int32! (JAX x64 disabled)
    const int*   batch = (const int*)d_in[2];    // int32!
    const float* W_l   = (const float*)d_in[3];
    const float* b_l   = (const float*)d_in[4];
    const float* W_r   = (const float*)d_in[5];
    const float* W_c   = (const float*)d_in[6];
    const float* b_c   = (const float*)d_in[7];
    float*       out   = (float*)d_out;

    zero_scratch<<<592, 256>>>();
    edge_scatter<<<12500, 256>>>(ei, x);
    count_nodes<<<(N_NODES + 255) / 256, 256>>>(batch);
    node_fused<<<(N_NODES + TILE_N - 1) / TILE_N, 256>>>(x, batch, W_l, b_l, W_r);
    finalize<<<N_GRAPHS, 256>>>(W_c, b_c, out);
}

// round 7
// speedup vs baseline: 1.0754x; 1.0754x over previous
#include <cuda_runtime.h>
#include <cstdint>

#define N_NODES 100000
#define N_EDGES 3200000
#define N_GRAPHS 512
#define IN_CH 50
#define HID 256
#define KDIM 100            // concatenated feature dim: [x(50) | agg(50)]
#define TILE_N 64           // nodes per block in fused GEMM
#define KC 25               // k-rows per smem chunk
#define NCHUNK 4            // KDIM / KC
#define FS_STRIDE 68        // padded Fs row (floats), 17 float4

// ---------------- device scratch ----------------
__device__ __align__(16) float g_agg[N_NODES * IN_CH];     // 20 MB neighbor sums
__device__ __align__(16) float g_cnt[N_NODES];             // edges per dst node
__device__ __align__(16) float g_pooled[N_GRAPHS * HID];   // per-graph h sums
__device__ __align__(16) float g_gcnt[N_GRAPHS];           // nodes per graph

// ---------------- packed f32x2 helpers (sm_100+) ----------------
__device__ __forceinline__ unsigned long long pack2(float lo, float hi) {
    unsigned long long r;
    asm("mov.b64 %0, {%1, %2};" : "=l"(r) : "f"(lo), "f"(hi));
    return r;
}
__device__ __forceinline__ void unpack2(unsigned long long v, float& lo, float& hi) {
    asm("mov.b64 {%0, %1}, %2;" : "=f"(lo), "=f"(hi) : "l"(v));
}
__device__ __forceinline__ void ffma2(unsigned long long& d,
                                      unsigned long long a, unsigned long long b) {
    asm("fma.rn.f32x2 %0, %1, %2, %0;" : "+l"(d) : "l"(a), "l"(b));
}

// ---------------- kernel 0: zero scratch ----------------
__global__ __launch_bounds__(256) void zero_scratch()
{
    int i = blockIdx.x * blockDim.x + threadIdx.x;
    int stride = gridDim.x * blockDim.x;
    for (; i < N_NODES * IN_CH / 4; i += stride)
        ((float4*)g_agg)[i] = make_float4(0.f, 0.f, 0.f, 0.f);
    for (i = blockIdx.x * blockDim.x + threadIdx.x; i < N_NODES; i += stride)
        g_cnt[i] = 0.f;
    for (i = blockIdx.x * blockDim.x + threadIdx.x; i < N_GRAPHS * HID; i += stride)
        g_pooled[i] = 0.f;
    for (i = blockIdx.x * blockDim.x + threadIdx.x; i < N_GRAPHS; i += stride)
        g_gcnt[i] = 0.f;
}

// ---------------- kernel 1: edge scatter-mean (sum + count) ----------------
__global__ __launch_bounds__(256) void edge_scatter(
    const int* __restrict__ ei, const float* __restrict__ x)
{
    int warp = (blockIdx.x * blockDim.x + threadIdx.x) >> 5;
    int lane = threadIdx.x & 31;
    int e = warp * 32 + lane;
    int s = ei[e];
    int d = ei[N_EDGES + e];
    const float2* x2 = (const float2*)x;
    #pragma unroll 4
    for (int i = 0; i < 32; i++) {
        int si = __shfl_sync(0xffffffffu, s, i);
        int di = __shfl_sync(0xffffffffu, d, i);
        if (lane < 25) {
            float2 v = x2[si * 25 + lane];
            atomicAdd((float2*)&g_agg[di * IN_CH + lane * 2], v);
        } else if (lane == 25) {
            atomicAdd(&g_cnt[di], 1.0f);
        }
    }
}

// ---------------- kernel 2: nodes per graph (atomic-free) ------------------
__global__ __launch_bounds__(256) void count_nodes(const int* __restrict__ batch)
{
    int i = blockIdx.x * blockDim.x + threadIdx.x;
    if (i >= N_NODES) return;
    int g = batch[i];
    if (i == 0 || batch[i - 1] != g) {
        int j = i + 1;
        while (j < N_NODES && batch[j] == g) j++;
        g_gcnt[g] = (float)(j - i);
    }
}

// ---------------- kernel 3: fused node GEMM + leakyReLU + pool-scatter -----
// Block: 256 threads, 64 nodes x 256 channels. Thread = 8 ch x 8 nodes,
// with channels packed pairwise into f32x2 accumulators (FFMA2 path).
__global__ __launch_bounds__(256) void node_fused(
    const float* __restrict__ x,
    const int* __restrict__ batch,
    const float* __restrict__ W_l, const float* __restrict__ b_l,
    const float* __restrict__ W_r)
{
    __shared__ float sW[KC * HID];          // 25600 B
    __shared__ float sF[KC * FS_STRIDE];    // 6800 B
    __shared__ float sInv[TILE_N];
    __shared__ int   sGid[TILE_N];

    int tid = threadIdx.x;
    int n0  = blockIdx.x * TILE_N;

    if (tid < TILE_N) {
        int node = n0 + tid;
        float c = 1.0f; int g = -1;
        if (node < N_NODES) { c = g_cnt[node]; g = batch[node]; }
        sInv[tid] = 1.0f / fmaxf(c, 1.0f);
        sGid[tid] = g;
    }

    int tc = tid & 31;   // channels tc*4..+3 and 128+tc*4..+3
    int tn = tid >> 5;   // nodes tn*8..tn*8+7

    // acc[a][b]: a = channel pair (0,1 -> tc*4+{0,1},{2,3}; 2,3 -> 128+tc*4+...)
    //            b = node j
    unsigned long long acc[4][8];
    #pragma unroll
    for (int a = 0; a < 4; a++)
        #pragma unroll
        for (int b = 0; b < 8; b++) acc[a][b] = 0ull;

    const float4* sW4 = (const float4*)sW;   // row = 64 float4
    const float4* sF4 = (const float4*)sF;   // row = 17 float4

    for (int kc = 0; kc < NCHUNK; kc++) {
        __syncthreads();
        // stage weights chunk: sW[kk][c], global k = kc*25+kk
        for (int idx = tid; idx < KC * HID; idx += 256) {
            int c  = idx / KC;
            int kk = idx - c * KC;
            int k  = kc * KC + kk;
            float v = (k < IN_CH) ? W_r[c * IN_CH + k]
                                  : W_l[c * IN_CH + k - IN_CH];
            sW[kk * HID + c] = v;
        }
        // stage feature chunk: sF[kk][n]
        for (int idx = tid; idx < KC * TILE_N; idx += 256) {
            int n  = idx / KC;
            int kk = idx - n * KC;
            int k  = kc * KC + kk;
            int node = n0 + n;
            float v = 0.0f;
            if (node < N_NODES) {
                v = (k < IN_CH) ? x[node * IN_CH + k]
                                : g_agg[node * IN_CH + k - IN_CH] * sInv[n];
            }
            sF[kk * FS_STRIDE + n] = v;
        }
        __syncthreads();

        #pragma unroll
        for (int kk = 0; kk < KC; kk++) {
            float4 w0 = sW4[kk * 64 + tc];
            float4 w1 = sW4[kk * 64 + 32 + tc];
            float4 f0 = sF4[kk * 17 + tn * 2];
            float4 f1 = sF4[kk * 17 + tn * 2 + 1];
            unsigned long long wp[4];
            wp[0] = pack2(w0.x, w0.y);
            wp[1] = pack2(w0.z, w0.w);
            wp[2] = pack2(w1.x, w1.y);
            wp[3] = pack2(w1.z, w1.w);
            float fs[8] = {f0.x, f0.y, f0.z, f0.w, f1.x, f1.y, f1.z, f1.w};
            unsigned long long fp[8];
            #pragma unroll
            for (int b = 0; b < 8; b++) fp[b] = pack2(fs[b], fs[b]);
            #pragma unroll
            for (int a = 0; a < 4; a++)
                #pragma unroll
                for (int b = 0; b < 8; b++)
                    ffma2(acc[a][b], wp[a], fp[b]);
        }
    }

    // epilogue: bias + leakyReLU, run-merged scalar REDs into g_pooled.
    const float4* bl4 = (const float4*)b_l;
    float4 bA = bl4[tc];
    float4 bB = bl4[32 + tc];
    float bias[8] = {bA.x, bA.y, bA.z, bA.w, bB.x, bB.y, bB.z, bB.w};
    int ch[8];
    #pragma unroll
    for (int a = 0; a < 4; a++) { ch[a] = tc * 4 + a; ch[4 + a] = 128 + tc * 4 + a; }

    float run[8];
    #pragma unroll
    for (int a = 0; a < 8; a++) run[a] = 0.0f;
    int runG = sGid[tn * 8];

    #pragma unroll
    for (int j = 0; j < 8; j++) {
        int g = sGid[tn * 8 + j];
        if (g != runG) {
            if (runG >= 0) {
                #pragma unroll
                for (int a = 0; a < 8; a++)
                    atomicAdd(&g_pooled[runG * HID + ch[a]], run[a]);
            }
            #pragma unroll
            for (int a = 0; a < 8; a++) run[a] = 0.0f;
            runG = g;
        }
        if (g >= 0) {
            float h[8];
            #pragma unroll
            for (int a = 0; a < 4; a++)
                unpack2(acc[a][j], h[2 * a], h[2 * a + 1]);
            #pragma unroll
            for (int a = 0; a < 8; a++) {
                float v = h[a] + bias[a];
                v = v > 0.f ? v : 0.01f * v;
                run[a] += v;
            }
        }
    }
    if (runG >= 0) {
        #pragma unroll
        for (int a = 0; a < 8; a++)
            atomicAdd(&g_pooled[runG * HID + ch[a]], run[a]);
    }
}

// ---------------- kernel 4: pooled mean + classifier ----------------
__global__ __launch_bounds__(256) void finalize(
    const float* __restrict__ W_c, const float* __restrict__ b_c,
    float* __restrict__ out)
{
    int g = blockIdx.x;
    int t = threadIdx.x;
    float inv = 1.0f / fmaxf(g_gcnt[g], 1.0f);
    float p = g_pooled[g * HID + t] * inv;
    float s0 = p * W_c[t];
    float s1 = p * W_c[HID + t];
    #pragma unroll
    for (int off = 16; off > 0; off >>= 1) {
        s0 += __shfl_down_sync(0xffffffffu, s0, off);
        s1 += __shfl_down_sync(0xffffffffu, s1, off);
    }
    __shared__ float sh0[8], sh1[8];
    int lane = t & 31, wid = t >> 5;
    if (lane == 0) { sh0[wid] = s0; sh1[wid] = s1; }
    __syncthreads();
    if (t == 0) {
        float t0 = b_c[0], t1 = b_c[1];
        #pragma unroll
        for (int w = 0; w < 8; w++) { t0 += sh0[w]; t1 += sh1[w]; }
        out[g * 2 + 0] = t0;
        out[g * 2 + 1] = t1;
    }
}

// ---------------- launch: kernel launches ONLY ----------------
extern "C" void kernel_launch(void* const* d_in, const int* in_sizes, int n_in,
                              void* d_out, int out_size)
{
    const float* x     = (const float*)d_in[0];
    const int*   ei    = (const int*)d_in[1];    // int32 (JAX x64 disabled)
    const int*   batch = (const int*)d_in[2];    // int32
    const float* W_l   = (const float*)d_in[3];
    const float* b_l   = (const float*)d_in[4];
    const float* W_r   = (const float*)d_in[5];
    const float* W_c   = (const float*)d_in[6];
    const float* b_c   = (const float*)d_in[7];
    float*       out   = (float*)d_out;

    zero_scratch<<<592, 256>>>();
    edge_scatter<<<12500, 256>>>(ei, x);
    count_nodes<<<(N_NODES + 255) / 256, 256>>>(batch);
    node_fused<<<(N_NODES + TILE_N - 1) / TILE_N, 256>>>(x, batch, W_l, b_l, W_r);
    finalize<<<N_GRAPHS, 256>>>(W_c, b_c, out);
}